// round 11
// baseline (speedup 1.0000x reference)
#include <cuda_runtime.h>
#include <mma.h>

using namespace nvcuda;

#define N_NODES 50000
#define N_EDGES 800000
#define D_IN    64
#define D_CAT   256   // SCALES * D_OUT = 4 * 64

// ---------------- scratch (static __device__: no allocations allowed) ----------
__device__ float4             g_A4[(size_t)N_NODES * (D_IN / 4)]; // 12.8 MB aggregated x
__device__ float              g_Wt[4 * 64 * 64];                  // Ws pre-rounded to tf32
__device__ float              g_dinv[N_NODES];                    // deg^{-1/2}
__device__ unsigned long long g_pack[N_NODES];                    // cnt<<52 | sum.32frac
                                                                  // zero at load; re-zeroed
                                                                  // by k_rsqrtself each run
__device__ unsigned           g_mm[2] = {0x7F800000u, 0u};        // min/max bits (idempotent)

// ---- 1) fused: min/max + packed raw degree + Ws->tf32 preconversion ------------
__global__ void k_prepdeg(const int* __restrict__ ei, const float* __restrict__ ew,
                          const float* __restrict__ Ws) {
    int gtid = blockIdx.x * blockDim.x + threadIdx.x;
    if (gtid < 4 * 64 * 64) g_Wt[gtid] = wmma::__float_to_tf32(Ws[gtid]);

    unsigned lmin = 0x7F800000u, lmax = 0u;
    for (int e = gtid; e < N_EDGES; e += gridDim.x * blockDim.x) {
        float w = ew[e];
        int   c = ei[N_EDGES + e];                     // dst = edge_index[1][e]
        unsigned b = __float_as_uint(w);               // nonneg: uint order == float order
        lmin = min(lmin, b);
        lmax = max(lmax, b);
        // pack: count in bits[52,64), raw-weight sum as 32-bit fixed point below
        unsigned long long pk = (1ULL << 52) |
                                (unsigned long long)(w * 4294967296.0f);
        atomicAdd(&g_pack[c], pk);
    }
    lmin = __reduce_min_sync(0xffffffffu, lmin);
    lmax = __reduce_max_sync(0xffffffffu, lmax);
    __shared__ unsigned smin[8], smax[8];
    int wid = threadIdx.x >> 5, lane = threadIdx.x & 31;
    if (lane == 0) { smin[wid] = lmin; smax[wid] = lmax; }
    __syncthreads();
    if (threadIdx.x == 0) {
        unsigned bmin = smin[0], bmax = smax[0];
        for (int w = 1; w < 8; w++) { bmin = min(bmin, smin[w]); bmax = max(bmax, smax[w]); }
        atomicMin(&g_mm[0], bmin);
        atomicMax(&g_mm[1], bmax);
    }
}

// ---- 2) dinv = rsqrt(deg), A = dinv^2 * x (one pass); resets g_pack ------------
__global__ void k_rsqrtself(const float* __restrict__ x) {
    int idx = blockIdx.x * blockDim.x + threadIdx.x;   // over 800000 float4s
    if (idx >= N_NODES * (D_IN / 4)) return;
    int row = idx >> 4;                                // 16 float4 per row

    unsigned long long v = g_pack[row];                // warp-broadcast (same row/16 lanes)
    float cnt = (float)(unsigned)(v >> 52);
    float sum = (float)(v & ((1ULL << 52) - 1)) * (1.0f / 4294967296.0f);
    float mn  = __uint_as_float(g_mm[0]);
    float inv = 1.0f / (__uint_as_float(g_mm[1]) - mn);
    float deg = 1.0f + (sum - cnt * mn) * inv;         // 1 = self-loop
    float di  = rsqrtf(deg);
    float dd  = di * di;

    float4 xv = ((const float4*)x)[idx];
    xv.x *= dd; xv.y *= dd; xv.z *= dd; xv.w *= dd;
    g_A4[idx] = xv;
    if ((idx & 15) == 0) {                             // one writer per row (loads of all
        g_dinv[row] = di;                              //  16 lanes precede this store)
        g_pack[row] = 0ull;                            // clean state for next replay
    }
}

// ---- 3) edge scatter: A[col] += norm * x[row], red.global.add.v4.f32 -----------
__device__ __forceinline__ void red_add_v4(float* p, float4 v) {
    asm volatile("red.global.add.v4.f32 [%0], {%1,%2,%3,%4};"
                 :: "l"(p), "f"(v.x), "f"(v.y), "f"(v.z), "f"(v.w)
                 : "memory");
}

__global__ void __launch_bounds__(256) k_edges(const int* __restrict__ ei,
                                               const float* __restrict__ ew,
                                               const float* __restrict__ x) {
    int lane  = threadIdx.x & 31;
    int gwarp = (blockIdx.x * blockDim.x + threadIdx.x) >> 5;
    int e = gwarp * 32 + lane;           // N_EDGES = 25000*32: no tail

    float mn  = __uint_as_float(g_mm[0]);
    float inv = 1.0f / (__uint_as_float(g_mm[1]) - mn);

    int   r = ei[e];                     // src = edge_index[0][e]
    int   c = ei[N_EDGES + e];           // dst = edge_index[1][e]
    float w = (ew[e] - mn) * inv;
    float nrm = g_dinv[r] * w * g_dinv[c];

    int half = lane >> 4;                // 0: even edge, 1: odd edge
    int q    = lane & 15;                // float4 index within the 64-float row

#pragma unroll 4
    for (int i = 0; i < 32; i += 2) {
        int   rr = __shfl_sync(0xffffffffu, r,   i + half);
        int   cc = __shfl_sync(0xffffffffu, c,   i + half);
        float nn = __shfl_sync(0xffffffffu, nrm, i + half);
        float4 v = ((const float4*)x)[(size_t)rr * 16 + q];
        v.x *= nn; v.y *= nn; v.z *= nn; v.w *= nn;
        red_add_v4((float*)(g_A4 + (size_t)cc * 16 + q), v);
    }
}

// ---- 4) GEMM out = A @ W_cat + b via TF32 wmma (m16n16k8) ----------------------
// Block: 32 rows x 256 cols, 8 warps. Warp (rt = wid&1, cg = wid>>1):
//   rows [rt*16, +16), cols [cg*64, +64) = 4 wmma tiles -> 4 acc frags (32 regs).
// All TF32 conversion hoisted: A converted during smem staging, W preconverted
// in g_Wt. 50000 % 16 == 0 -> every 16-row tile fully valid or fully OOB.
__global__ void __launch_bounds__(256) k_gemm(const float* __restrict__ bs,
                                              float* __restrict__ out) {
    __shared__ float as[32 * 64];       //  8 KB  A tile (tf32-rounded)
    __shared__ float bias[16 * 256];    // 16 KB  bias replicated over 16 rows

    const int tid  = threadIdx.x;
    const int wid  = tid >> 5;
    const int row0 = blockIdx.x * 32;
    const float* A = (const float*)g_A4;

    // stage A (32x64), tf32-rounded at store
#pragma unroll
    for (int s = 0; s < 8; s++) {
        int idx = tid + 256 * s;
        int r = idx >> 6;
        int gr = row0 + r;
        float v = (gr < N_NODES) ? A[(size_t)gr * D_IN + (idx & 63)] : 0.0f;
        as[idx] = wmma::__float_to_tf32(v);
    }
    // stage bias, replicated across 16 rows
#pragma unroll
    for (int s = 0; s < 16; s++) {
        int idx = tid + 256 * s;
        bias[idx] = bs[idx & 255];
    }
    __syncthreads();

    const int rt = wid & 1;             // row tile 0..1
    const int cg = wid >> 1;            // col group 0..3 (one 64-col scale each)
    const int cbase = cg * 64;

    wmma::fragment<wmma::accumulator, 16, 16, 8, float> acc[4];
#pragma unroll
    for (int ct = 0; ct < 4; ct++)
        wmma::load_matrix_sync(acc[ct], &bias[cbase + ct * 16], 256, wmma::mem_row_major);

#pragma unroll
    for (int k0 = 0; k0 < 8; k0++) {    // K = 64 in steps of 8
        wmma::fragment<wmma::matrix_a, 16, 16, 8, wmma::precision::tf32,
                       wmma::row_major> a;
        wmma::load_matrix_sync(a, &as[rt * 16 * 64 + k0 * 8], 64);
#pragma unroll
        for (int ct = 0; ct < 4; ct++) {
            // W_cat[k][c], c in scale cg: g_Wt + cg*4096 + k*64 + (c&63), stride 64
            wmma::fragment<wmma::matrix_b, 16, 16, 8, wmma::precision::tf32,
                           wmma::row_major> b;
            wmma::load_matrix_sync(b, g_Wt + cg * 4096 + k0 * 8 * 64 + ct * 16, 64);
            wmma::mma_sync(acc[ct], a, b, acc[ct]);
        }
    }

    int gr0 = row0 + rt * 16;
    if (gr0 + 16 <= N_NODES) {          // 50000 % 16 == 0: tile all-in or all-out
#pragma unroll
        for (int ct = 0; ct < 4; ct++)
            wmma::store_matrix_sync(&out[(size_t)gr0 * D_CAT + cbase + ct * 16],
                                    acc[ct], D_CAT, wmma::mem_row_major);
    }
}

// ---------------- launch -------------------------------------------------------
extern "C" void kernel_launch(void* const* d_in, const int* in_sizes, int n_in,
                              void* d_out, int out_size) {
    // Resolve inputs by element count (all five distinct):
    //   x=3,200,000 f32 | edge_index=1,600,000 i32 | edge_weight=800,000 f32
    //   Ws=16,384 f32   | bs=256 f32
    const float* x  = nullptr;
    const int*   ei = nullptr;
    const float* ew = nullptr;
    const float* Ws = nullptr;
    const float* bs = nullptr;
    for (int i = 0; i < n_in; i++) {
        switch (in_sizes[i]) {
            case 3200000: x  = (const float*)d_in[i]; break;
            case 1600000: ei = (const int*)d_in[i];   break;
            case  800000: ew = (const float*)d_in[i]; break;
            case   16384: Ws = (const float*)d_in[i]; break;
            case     256: bs = (const float*)d_in[i]; break;
        }
    }
    float* out = (float*)d_out;  // [50000, 256]

    k_prepdeg<<<256, 256>>>(ei, ew, Ws);                        // minmax + degree + W->tf32
    k_rsqrtself<<<(N_NODES * 16 + 255) / 256, 256>>>(x);        // dinv + A=dinv^2*x + reset
    k_edges<<<(N_EDGES / 32) / 8, 256>>>(ei, ew, x);            // 3125 blocks, v4 REDs
    k_gemm<<<(N_NODES + 31) / 32, 256>>>(bs, out);              // TF32 wmma GEMM + bias
}

// round 13
// speedup vs baseline: 1.3609x; 1.3609x over previous
#include <cuda_runtime.h>
#include <mma.h>

using namespace nvcuda;

#define N_NODES 50000
#define N_EDGES 800000
#define D_IN    64
#define D_CAT   256   // SCALES * D_OUT = 4 * 64

// ---------------- scratch (static __device__: no allocations allowed) ----------
__device__ float4             g_A4[(size_t)N_NODES * (D_IN / 4)]; // 12.8 MB aggregated x
__device__ float              g_Wt[4 * 64 * 64];                  // Ws pre-rounded to tf32
__device__ float              g_dinv[N_NODES];                    // deg^{-1/2}
__device__ unsigned long long g_pack[N_NODES];                    // cnt<<52 | sum.32frac
                                                                  // zero at load; re-zeroed
                                                                  // by k_rsqrtself each run
__device__ unsigned           g_mm[2] = {0x7F800000u, 0u};        // min/max bits (idempotent)

// ---- 1) fused: min/max + packed raw degree + Ws->tf32 preconversion ------------
__global__ void k_prepdeg(const int* __restrict__ ei, const float* __restrict__ ew,
                          const float* __restrict__ Ws) {
    int gtid = blockIdx.x * blockDim.x + threadIdx.x;
    if (gtid < 4 * 64 * 64) g_Wt[gtid] = wmma::__float_to_tf32(Ws[gtid]);

    unsigned lmin = 0x7F800000u, lmax = 0u;
    for (int e = gtid; e < N_EDGES; e += gridDim.x * blockDim.x) {
        float w = ew[e];
        int   c = ei[N_EDGES + e];                     // dst = edge_index[1][e]
        unsigned b = __float_as_uint(w);               // nonneg: uint order == float order
        lmin = min(lmin, b);
        lmax = max(lmax, b);
        // pack: count in bits[52,64), raw-weight sum as 32-bit fixed point below
        unsigned long long pk = (1ULL << 52) |
                                (unsigned long long)(w * 4294967296.0f);
        atomicAdd(&g_pack[c], pk);
    }
    lmin = __reduce_min_sync(0xffffffffu, lmin);
    lmax = __reduce_max_sync(0xffffffffu, lmax);
    __shared__ unsigned smin[8], smax[8];
    int wid = threadIdx.x >> 5, lane = threadIdx.x & 31;
    if (lane == 0) { smin[wid] = lmin; smax[wid] = lmax; }
    __syncthreads();
    if (threadIdx.x == 0) {
        unsigned bmin = smin[0], bmax = smax[0];
        for (int w = 1; w < 8; w++) { bmin = min(bmin, smin[w]); bmax = max(bmax, smax[w]); }
        atomicMin(&g_mm[0], bmin);
        atomicMax(&g_mm[1], bmax);
    }
}

// ---- 2) dinv = rsqrt(deg), A = dinv^2 * x (one pass); resets g_pack ------------
__global__ void k_rsqrtself(const float* __restrict__ x) {
    int idx = blockIdx.x * blockDim.x + threadIdx.x;   // over 800000 float4s
    if (idx >= N_NODES * (D_IN / 4)) return;
    int row = idx >> 4;                                // 16 float4 per row

    unsigned long long v = g_pack[row];                // warp-broadcast (same row/16 lanes)
    float cnt = (float)(unsigned)(v >> 52);
    float sum = (float)(v & ((1ULL << 52) - 1)) * (1.0f / 4294967296.0f);
    float mn  = __uint_as_float(g_mm[0]);
    float inv = 1.0f / (__uint_as_float(g_mm[1]) - mn);
    float deg = 1.0f + (sum - cnt * mn) * inv;         // 1 = self-loop
    float di  = rsqrtf(deg);
    float dd  = di * di;

    float4 xv = ((const float4*)x)[idx];
    xv.x *= dd; xv.y *= dd; xv.z *= dd; xv.w *= dd;
    g_A4[idx] = xv;
    if ((idx & 15) == 0) {                             // one writer per row (loads of all
        g_dinv[row] = di;                              //  16 lanes precede this store)
        g_pack[row] = 0ull;                            // clean state for next replay
    }
}

// ---- 3) edge scatter: A[col] += norm * x[row], red.global.add.v4.f32 -----------
__device__ __forceinline__ void red_add_v4(float* p, float4 v) {
    asm volatile("red.global.add.v4.f32 [%0], {%1,%2,%3,%4};"
                 :: "l"(p), "f"(v.x), "f"(v.y), "f"(v.z), "f"(v.w)
                 : "memory");
}

__global__ void __launch_bounds__(256) k_edges(const int* __restrict__ ei,
                                               const float* __restrict__ ew,
                                               const float* __restrict__ x) {
    int lane  = threadIdx.x & 31;
    int gwarp = (blockIdx.x * blockDim.x + threadIdx.x) >> 5;
    int e = gwarp * 32 + lane;           // N_EDGES = 25000*32: no tail

    float mn  = __uint_as_float(g_mm[0]);
    float inv = 1.0f / (__uint_as_float(g_mm[1]) - mn);

    int   r = ei[e];                     // src = edge_index[0][e]
    int   c = ei[N_EDGES + e];           // dst = edge_index[1][e]
    float w = (ew[e] - mn) * inv;
    float nrm = g_dinv[r] * w * g_dinv[c];

    int half = lane >> 4;                // 0: even edge, 1: odd edge
    int q    = lane & 15;                // float4 index within the 64-float row

#pragma unroll 4
    for (int i = 0; i < 32; i += 2) {
        int   rr = __shfl_sync(0xffffffffu, r,   i + half);
        int   cc = __shfl_sync(0xffffffffu, c,   i + half);
        float nn = __shfl_sync(0xffffffffu, nrm, i + half);
        float4 v = ((const float4*)x)[(size_t)rr * 16 + q];
        v.x *= nn; v.y *= nn; v.z *= nn; v.w *= nn;
        red_add_v4((float*)(g_A4 + (size_t)cc * 16 + q), v);
    }
}

// ---- 4) GEMM out = A @ W_cat + b via raw mma.sync m16n8k8 tf32 -----------------
// Block: 64 rows x 256 cols, 8 warps. Warp w: rows [(w&1)*32,+32), cols
// [(w>>1)*64,+64) = 2 m-tiles x 8 n-tiles = 16 acc frags.  B frags (2 LDG/lane,
// L1-resident 64 KB) are reused across both m-tiles; A frags come from smem
// padded to stride 68 (bank = 4*row+col -> conflict-free). Bias is the
// accumulator init. 50000 % 16 == 0 -> per-m16-tile all-in/all-out stores.
__device__ __forceinline__ void mma_tf32(float* d, const unsigned* a,
                                         const unsigned* b) {
    asm volatile(
        "mma.sync.aligned.m16n8k8.row.col.f32.tf32.tf32.f32 "
        "{%0,%1,%2,%3}, {%4,%5,%6,%7}, {%8,%9}, {%0,%1,%2,%3};\n"
        : "+f"(d[0]), "+f"(d[1]), "+f"(d[2]), "+f"(d[3])
        : "r"(a[0]), "r"(a[1]), "r"(a[2]), "r"(a[3]), "r"(b[0]), "r"(b[1]));
}

#define AS_LD 68   // padded leading dim for the A tile

__global__ void __launch_bounds__(256) k_gemm(const float* __restrict__ bs,
                                              float* __restrict__ out) {
    __shared__ float as[64 * AS_LD];    // 17.4 KB, tf32-rounded A tile

    const int tid  = threadIdx.x;
    const int w    = tid >> 5;
    const int lane = tid & 31;
    const int g    = lane >> 2;         // group id (row within m16 tile)
    const int tg   = lane & 3;          // thread-in-group (k / col-pair select)
    const int row0 = blockIdx.x * 64;

    // ---- stage A (64x64) as tf32, padded stride, float4 stores ----
#pragma unroll
    for (int s = 0; s < 4; s++) {
        int i  = tid + 256 * s;         // 0..1023 float4 slots
        int r  = i >> 4, c4 = i & 15;
        int gr = row0 + r;
        float4 v = (gr < N_NODES) ? g_A4[(size_t)gr * 16 + c4]
                                  : make_float4(0.f, 0.f, 0.f, 0.f);
        v.x = wmma::__float_to_tf32(v.x); v.y = wmma::__float_to_tf32(v.y);
        v.z = wmma::__float_to_tf32(v.z); v.w = wmma::__float_to_tf32(v.w);
        *(float4*)&as[r * AS_LD + c4 * 4] = v;
    }
    __syncthreads();

    const int mrow  = (w & 1) * 32;     // warp's row offset in tile
    const int cg    = w >> 1;           // scale index 0..3 (64 cols each)
    const int cbase = cg * 64;

    // ---- init accumulators from bias (d2/d3 share cols with d0/d1) ----
    float acc[2][8][4];
#pragma unroll
    for (int nt = 0; nt < 8; nt++) {
        float2 bb = *(const float2*)&bs[cbase + nt * 8 + 2 * tg];
#pragma unroll
        for (int mt = 0; mt < 2; mt++) {
            acc[mt][nt][0] = bb.x; acc[mt][nt][1] = bb.y;
            acc[mt][nt][2] = bb.x; acc[mt][nt][3] = bb.y;
        }
    }

    // ---- main loop: K = 64 in 8 steps of 8 ----
#pragma unroll
    for (int k0 = 0; k0 < 8; k0++) {
        const int kb = k0 * 8;
        unsigned a[2][4];
#pragma unroll
        for (int mt = 0; mt < 2; mt++) {
            int r = mrow + mt * 16 + g;
            a[mt][0] = __float_as_uint(as[r * AS_LD + kb + tg]);
            a[mt][1] = __float_as_uint(as[(r + 8) * AS_LD + kb + tg]);
            a[mt][2] = __float_as_uint(as[r * AS_LD + kb + tg + 4]);
            a[mt][3] = __float_as_uint(as[(r + 8) * AS_LD + kb + tg + 4]);
        }
#pragma unroll
        for (int nt = 0; nt < 8; nt++) {
            // B[k][n]: g_Wt[cg*4096 + k*64 + n_in_scale], n_in_scale = nt*8 + g
            const float* wp = g_Wt + cg * 4096 + (size_t)(kb + tg) * 64 + nt * 8 + g;
            unsigned b[2];
            b[0] = __float_as_uint(wp[0]);
            b[1] = __float_as_uint(wp[4 * 64]);       // k + 4
            mma_tf32(acc[0][nt], a[0], b);
            mma_tf32(acc[1][nt], a[1], b);
        }
    }

    // ---- epilogue: float2 stores; 50000 % 16 == 0 -> whole-tile predicate ----
#pragma unroll
    for (int mt = 0; mt < 2; mt++) {
        int gr0 = row0 + mrow + mt * 16;
        if (gr0 + 16 > N_NODES) continue;
#pragma unroll
        for (int nt = 0; nt < 8; nt++) {
            int col = cbase + nt * 8 + 2 * tg;
            *(float2*)&out[(size_t)(gr0 + g) * D_CAT + col] =
                make_float2(acc[mt][nt][0], acc[mt][nt][1]);
            *(float2*)&out[(size_t)(gr0 + 8 + g) * D_CAT + col] =
                make_float2(acc[mt][nt][2], acc[mt][nt][3]);
        }
    }
}

// ---------------- launch -------------------------------------------------------
extern "C" void kernel_launch(void* const* d_in, const int* in_sizes, int n_in,
                              void* d_out, int out_size) {
    // Resolve inputs by element count (all five distinct):
    //   x=3,200,000 f32 | edge_index=1,600,000 i32 | edge_weight=800,000 f32
    //   Ws=16,384 f32   | bs=256 f32
    const float* x  = nullptr;
    const int*   ei = nullptr;
    const float* ew = nullptr;
    const float* Ws = nullptr;
    const float* bs = nullptr;
    for (int i = 0; i < n_in; i++) {
        switch (in_sizes[i]) {
            case 3200000: x  = (const float*)d_in[i]; break;
            case 1600000: ei = (const int*)d_in[i];   break;
            case  800000: ew = (const float*)d_in[i]; break;
            case   16384: Ws = (const float*)d_in[i]; break;
            case     256: bs = (const float*)d_in[i]; break;
        }
    }
    float* out = (float*)d_out;  // [50000, 256]

    k_prepdeg<<<256, 256>>>(ei, ew, Ws);                        // minmax + degree + W->tf32
    k_rsqrtself<<<(N_NODES * 16 + 255) / 256, 256>>>(x);        // dinv + A=dinv^2*x + reset
    k_edges<<<(N_EDGES / 32) / 8, 256>>>(ei, ew, x);            // 3125 blocks, v4 REDs
    k_gemm<<<(N_NODES + 63) / 64, 256>>>(bs, out);              // raw mma.sync GEMM + bias
}